// round 14
// baseline (speedup 1.0000x reference)
#include <cuda_runtime.h>
#include <cuda_fp16.h>
#include <math.h>
#include <stdint.h>

#define DIM   1024
#define HEADS 16
#define HDIM  64
#define MLP   4096
#define BB    4
#define SS    2048
#define TT    (BB*SS)   // 8192 tokens

// ---------------- scratch (device globals; no allocation) ----------------
__device__ __half h_xn[(size_t)TT*DIM];
__device__ __half h_qkv[(size_t)TT*3*DIM];
__device__ __half h_attn[(size_t)TT*DIM];
__device__ float  g_x1[(size_t)TT*DIM];
__device__ __half h_h[(size_t)TT*MLP];
__device__ __half h_qkvT[(size_t)3*DIM*DIM];
__device__ __half h_projT[(size_t)DIM*DIM];
__device__ __half h_fc1T[(size_t)DIM*MLP];
__device__ __half h_fc2T[(size_t)MLP*DIM];

// ---------------- ptx helpers ----------------
__device__ __forceinline__ void mma_f16(float* c, const uint32_t* a, const uint32_t* b) {
    asm volatile(
        "mma.sync.aligned.m16n8k16.row.col.f32.f16.f16.f32 "
        "{%0,%1,%2,%3}, {%4,%5,%6,%7}, {%8,%9}, {%0,%1,%2,%3};"
        : "+f"(c[0]), "+f"(c[1]), "+f"(c[2]), "+f"(c[3])
        : "r"(a[0]), "r"(a[1]), "r"(a[2]), "r"(a[3]), "r"(b[0]), "r"(b[1]));
}

__device__ __forceinline__ void ldmx4(uint32_t& r0, uint32_t& r1, uint32_t& r2, uint32_t& r3,
                                      const __half* p) {
    uint32_t a = (uint32_t)__cvta_generic_to_shared((void*)p);
    asm volatile("ldmatrix.sync.aligned.m8n8.x4.shared.b16 {%0,%1,%2,%3}, [%4];"
                 : "=r"(r0), "=r"(r1), "=r"(r2), "=r"(r3) : "r"(a));
}

__device__ __forceinline__ void ldmx4t(uint32_t& r0, uint32_t& r1, uint32_t& r2, uint32_t& r3,
                                       const __half* p) {
    uint32_t a = (uint32_t)__cvta_generic_to_shared((void*)p);
    asm volatile("ldmatrix.sync.aligned.m8n8.x4.trans.shared.b16 {%0,%1,%2,%3}, [%4];"
                 : "=r"(r0), "=r"(r1), "=r"(r2), "=r"(r3) : "r"(a));
}

__device__ __forceinline__ void cpa16(__half* dst, const __half* src) {
    uint32_t s = (uint32_t)__cvta_generic_to_shared((void*)dst);
    asm volatile("cp.async.cg.shared.global [%0], [%1], 16;" :: "r"(s), "l"(src));
}
#define CP_COMMIT() asm volatile("cp.async.commit_group;" ::: "memory")
#define CP_WAIT1()  asm volatile("cp.async.wait_group 1;" ::: "memory")

// ---------------- LayerNorm: fp32 in -> fp16 out ----------------
__global__ __launch_bounds__(256)
void ln_kernel(const float* __restrict__ x, const float* __restrict__ w,
               const float* __restrict__ b, __half* __restrict__ out) {
    int row = blockIdx.x;
    int tid = threadIdx.x;
    const float4* xr = (const float4*)(x + (size_t)row * DIM);
    float4 v = xr[tid];
    float s  = v.x + v.y + v.z + v.w;
    float ss = v.x*v.x + v.y*v.y + v.z*v.z + v.w*v.w;
    #pragma unroll
    for (int o = 16; o; o >>= 1) {
        s  += __shfl_xor_sync(0xffffffffu, s,  o);
        ss += __shfl_xor_sync(0xffffffffu, ss, o);
    }
    __shared__ float red0[8], red1[8];
    int wid = tid >> 5, lid = tid & 31;
    if (lid == 0) { red0[wid] = s; red1[wid] = ss; }
    __syncthreads();
    float sum = 0.f, sumsq = 0.f;
    #pragma unroll
    for (int i = 0; i < 8; i++) { sum += red0[i]; sumsq += red1[i]; }
    float mu   = sum * (1.0f / DIM);
    float var  = sumsq * (1.0f / DIM) - mu * mu;
    float rstd = rsqrtf(var + 1e-5f);
    float4 wv = ((const float4*)w)[tid];
    float4 bv = ((const float4*)b)[tid];
    __half2* o2 = (__half2*)(out + (size_t)row * DIM);
    o2[tid*2+0] = __floats2half2_rn((v.x - mu)*rstd*wv.x + bv.x,
                                    (v.y - mu)*rstd*wv.y + bv.y);
    o2[tid*2+1] = __floats2half2_rn((v.z - mu)*rstd*wv.z + bv.z,
                                    (v.w - mu)*rstd*wv.w + bv.w);
}

// ---------------- weight transpose [K,N] fp32 -> [N,K] fp16 ----------------
__global__ __launch_bounds__(256)
void transpose_h_kernel(const float* __restrict__ in, __half* __restrict__ out,
                        int K, int N) {
    __shared__ float tile[32][33];
    int bx = blockIdx.x;
    int by = blockIdx.y;
    int tx = threadIdx.x & 31;
    int ty = threadIdx.x >> 5;
    #pragma unroll
    for (int i = 0; i < 32; i += 8)
        tile[ty + i][tx] = in[(size_t)(by * 32 + ty + i) * N + bx * 32 + tx];
    __syncthreads();
    #pragma unroll
    for (int i = 0; i < 32; i += 8)
        out[(size_t)(bx * 32 + ty + i) * K + by * 32 + tx] = __float2half_rn(tile[tx][ty + i]);
}

// ---------------- fp16 mma GEMM: BK=64, 3-stage cp.async + ldmatrix, 1 sync/chunk ----------------
// BM=BN=128, 128 threads (4 warps, warp tile 64x64), occupancy 2.
// Halved barrier count vs BK=32 (16 barriers per K=1024 instead of 32).
#define GLDA 72                       // 64 halves + pad 8 (row stride 36 words: conflict-free)
#define STG_H (2 * 128 * GLDA)        // halves per stage (A 128 rows, B 128 rows)

template <int EPI>
__global__ __launch_bounds__(128, 2)
void gemm_h(int M, int N, int K,
            const __half* __restrict__ A, const __half* __restrict__ Bt,
            const float* __restrict__ bias, const float* __restrict__ R,
            void* __restrict__ Cout) {
    __shared__ __half sh[3 * STG_H];

    int tid = threadIdx.x;
    int wid = tid >> 5, lane = tid & 31;
    int gid = lane >> 2, tg = lane & 3;
    int wm = wid & 1, wn = wid >> 1;
    int bx = blockIdx.x, by = blockIdx.y;

    const __half* Ab = A  + (size_t)(by * 128) * K;
    const __half* Bb = Bt + (size_t)(bx * 128) * K;

    float acc[4][8][4];
    #pragma unroll
    for (int i = 0; i < 4; i++)
        #pragma unroll
        for (int j = 0; j < 8; j++)
            #pragma unroll
            for (int c = 0; c < 4; c++) acc[i][j][c] = 0.f;

    int NC = K / 64;

    auto issue = [&](int s) {
        if (s < NC) {
            __half* sa = sh + (s % 3) * STG_H;
            __half* sb = sa + 128 * GLDA;
            int kb = s * 64;
            #pragma unroll
            for (int it = 0; it < 8; it++) {      // 128 rows x 64 halves = 1024 x 16B chunks
                int idx = it * 128 + tid;
                int r = idx >> 3, c8 = (idx & 7) * 8;
                cpa16(sa + r * GLDA + c8, Ab + (size_t)r * K + kb + c8);
                cpa16(sb + r * GLDA + c8, Bb + (size_t)r * K + kb + c8);
            }
        }
        CP_COMMIT();
    };

    issue(0); issue(1);

    for (int kc = 0; kc < NC; kc++) {
        CP_WAIT1();
        __syncthreads();
        issue(kc + 2);   // refills buffer (kc-1)%3: all warps past compute(kc-1)

        const __half* Ac = sh + (kc % 3) * STG_H;
        const __half* Bc = Ac + 128 * GLDA;

        #pragma unroll
        for (int kk = 0; kk < 64; kk += 16) {
            uint32_t af[4][4];
            #pragma unroll
            for (int mf = 0; mf < 4; mf++) {
                const __half* p = Ac + (wm * 64 + mf * 16 + (lane & 15)) * GLDA
                                  + kk + (lane >> 4) * 8;
                ldmx4(af[mf][0], af[mf][1], af[mf][2], af[mf][3], p);
            }
            uint32_t bf[8][2];
            #pragma unroll
            for (int pj = 0; pj < 4; pj++) {
                const __half* p = Bc + (wn * 64 + (pj * 2 + (lane >> 4)) * 8 + (lane & 7)) * GLDA
                                  + kk + ((lane >> 3) & 1) * 8;
                ldmx4(bf[2*pj][0], bf[2*pj][1], bf[2*pj+1][0], bf[2*pj+1][1], p);
            }
            #pragma unroll
            for (int mf = 0; mf < 4; mf++)
                #pragma unroll
                for (int nb = 0; nb < 8; nb++)
                    mma_f16(acc[mf][nb], af[mf], bf[nb]);
        }
    }

    // epilogue
    int colW = bx * 128 + wn * 64;
    #pragma unroll
    for (int mf = 0; mf < 4; mf++) {
        #pragma unroll
        for (int r2 = 0; r2 < 2; r2++) {
            int row = by * 128 + wm * 64 + mf * 16 + gid + r2 * 8;
            #pragma unroll
            for (int nb = 0; nb < 8; nb++) {
                int gcol = colW + nb * 8 + 2 * tg;
                float t0 = acc[mf][nb][r2 * 2 + 0] + bias[gcol];
                float t1 = acc[mf][nb][r2 * 2 + 1] + bias[gcol + 1];
                if (EPI == 1) {
                    t0 = 0.5f * t0 * (1.0f + erff(t0 * 0.70710678118654752f));
                    t1 = 0.5f * t1 * (1.0f + erff(t1 * 0.70710678118654752f));
                }
                if (EPI == 2) {
                    float2 rv = *(const float2*)(R + (size_t)row * N + gcol);
                    t0 += rv.x; t1 += rv.y;
                    *(float2*)((float*)Cout + (size_t)row * N + gcol) = make_float2(t0, t1);
                } else {
                    *(__half2*)((__half*)Cout + (size_t)row * N + gcol) = __floats2half2_rn(t0, t1);
                }
            }
        }
    }
}

// ---------------- causal flash attention: 128 q/CTA, 8 warps, V via ldmatrix.trans ----------------
#define KLD 72
#define ATILE (64 * KLD)

__global__ __launch_bounds__(256)
void attn_mma(const __half* __restrict__ qkv, __half* __restrict__ out) {
    int qt = blockIdx.x, bh = blockIdx.y;     // qt: 0..15 (128-query tiles)
    int b = bh >> 4, h = bh & 15;
    int tid = threadIdx.x;
    int wid = tid >> 5, lane = tid & 31;
    int gid = lane >> 2, tg = lane & 3;
    int q0 = qt * 128;
    int ntiles = 2 * qt + 2;

    __shared__ __half Ks3[3 * ATILE];   // [key][dim]
    __shared__ __half Vs3[3 * ATILE];   // [key][dim]

    auto issueA = [&](int s) {
        if (s < ntiles) {
            __half* ka = Ks3 + (s % 3) * ATILE;
            __half* va = Vs3 + (s % 3) * ATILE;
            #pragma unroll
            for (int it = 0; it < 2; it++) {
                int idx = it * 256 + tid;
                int r = idx >> 3, c8 = (idx & 7) * 8;
                const __half* src = qkv + ((size_t)(b * SS) + s * 64 + r) * (3 * DIM) + h * HDIM + c8;
                cpa16(ka + r * KLD + c8, src + DIM);
                cpa16(va + r * KLD + c8, src + 2 * DIM);
            }
        }
        CP_COMMIT();
    };

    uint32_t qa[4][4];
    {
        const __half* Q0 = qkv + ((size_t)(b * SS) + q0 + wid * 16 + gid) * (3 * DIM) + h * HDIM + 2 * tg;
        const __half* Q1 = Q0 + (size_t)8 * (3 * DIM);
        #pragma unroll
        for (int kcc = 0; kcc < 4; kcc++) {
            qa[kcc][0] = *(const uint32_t*)(Q0 + kcc * 16);
            qa[kcc][1] = *(const uint32_t*)(Q1 + kcc * 16);
            qa[kcc][2] = *(const uint32_t*)(Q0 + kcc * 16 + 8);
            qa[kcc][3] = *(const uint32_t*)(Q1 + kcc * 16 + 8);
        }
    }

    issueA(0); issueA(1);

    float oacc[8][4];
    #pragma unroll
    for (int nb = 0; nb < 8; nb++)
        #pragma unroll
        for (int c = 0; c < 4; c++) oacc[nb][c] = 0.f;
    float m0 = -1e30f, m1 = -1e30f, l0 = 0.f, l1 = 0.f;
    int rg0 = q0 + wid * 16 + gid;
    int rg1 = rg0 + 8;

    int lm_row = ((lane >> 4)) * 8 + (lane & 7);
    int lm_koff = ((lane >> 3) & 1) * 8;
    int vt_row = (lane & 7) + ((lane >> 3) & 1) * 8;
    int vt_col = (lane >> 4) * 8;

    for (int jt = 0; jt < ntiles; jt++) {
        CP_WAIT1();
        __syncthreads();
        issueA(jt + 2);

        const __half* Kc = Ks3 + (jt % 3) * ATILE;
        const __half* Vc = Vs3 + (jt % 3) * ATILE;

        // S = Q @ K^T
        float sacc[8][4];
        #pragma unroll
        for (int nb = 0; nb < 8; nb++)
            #pragma unroll
            for (int c = 0; c < 4; c++) sacc[nb][c] = 0.f;
        #pragma unroll
        for (int kcc = 0; kcc < 4; kcc++) {
            uint32_t bf[8][2];
            #pragma unroll
            for (int pj = 0; pj < 4; pj++) {
                const __half* p = Kc + (pj * 16 + lm_row) * KLD + kcc * 16 + lm_koff;
                ldmx4(bf[2*pj][0], bf[2*pj][1], bf[2*pj+1][0], bf[2*pj+1][1], p);
            }
            #pragma unroll
            for (int nb = 0; nb < 8; nb++)
                mma_f16(sacc[nb], qa[kcc], bf[nb]);
        }

        const float sc = 0.125f;
        float tm0 = -1e30f, tm1 = -1e30f;
        bool need_mask = (jt >= 2 * qt);
        #pragma unroll
        for (int nb = 0; nb < 8; nb++) {
            int col = jt * 64 + nb * 8 + 2 * tg;
            float s0 = sacc[nb][0] * sc, s1 = sacc[nb][1] * sc;
            float s2 = sacc[nb][2] * sc, s3 = sacc[nb][3] * sc;
            if (need_mask) {
                if (col     > rg0) s0 = -1e30f;
                if (col + 1 > rg0) s1 = -1e30f;
                if (col     > rg1) s2 = -1e30f;
                if (col + 1 > rg1) s3 = -1e30f;
            }
            sacc[nb][0] = s0; sacc[nb][1] = s1; sacc[nb][2] = s2; sacc[nb][3] = s3;
            tm0 = fmaxf(tm0, fmaxf(s0, s1));
            tm1 = fmaxf(tm1, fmaxf(s2, s3));
        }
        tm0 = fmaxf(tm0, __shfl_xor_sync(0xffffffffu, tm0, 1));
        tm0 = fmaxf(tm0, __shfl_xor_sync(0xffffffffu, tm0, 2));
        tm1 = fmaxf(tm1, __shfl_xor_sync(0xffffffffu, tm1, 1));
        tm1 = fmaxf(tm1, __shfl_xor_sync(0xffffffffu, tm1, 2));

        float mn0 = fmaxf(m0, tm0), mn1 = fmaxf(m1, tm1);
        float cr0 = __expf(m0 - mn0), cr1 = __expf(m1 - mn1);
        l0 *= cr0; l1 *= cr1;
        #pragma unroll
        for (int nb = 0; nb < 8; nb++) {
            oacc[nb][0] *= cr0; oacc[nb][1] *= cr0;
            oacc[nb][2] *= cr1; oacc[nb][3] *= cr1;
        }
        uint32_t pa01[8], pa23[8];
        #pragma unroll
        for (int nb = 0; nb < 8; nb++) {
            float p0 = __expf(sacc[nb][0] - mn0);
            float p1 = __expf(sacc[nb][1] - mn0);
            float p2 = __expf(sacc[nb][2] - mn1);
            float p3 = __expf(sacc[nb][3] - mn1);
            l0 += p0 + p1; l1 += p2 + p3;
            __half2 h01 = __floats2half2_rn(p0, p1);
            __half2 h23 = __floats2half2_rn(p2, p3);
            pa01[nb] = *(uint32_t*)&h01;
            pa23[nb] = *(uint32_t*)&h23;
        }
        m0 = mn0; m1 = mn1;

        // O += P @ V  (B-fragments via ldmatrix.trans from [key][dim] tile)
        #pragma unroll
        for (int kcc = 0; kcc < 4; kcc++) {
            uint32_t aa[4] = { pa01[2*kcc], pa23[2*kcc], pa01[2*kcc+1], pa23[2*kcc+1] };
            uint32_t bf[8][2];
            #pragma unroll
            for (int pj = 0; pj < 4; pj++) {
                const __half* p = Vc + (kcc * 16 + vt_row) * KLD + pj * 16 + vt_col;
                ldmx4t(bf[2*pj][0], bf[2*pj][1], bf[2*pj+1][0], bf[2*pj+1][1], p);
            }
            #pragma unroll
            for (int nb = 0; nb < 8; nb++)
                mma_f16(oacc[nb], aa, bf[nb]);
        }
    }

    l0 += __shfl_xor_sync(0xffffffffu, l0, 1);
    l0 += __shfl_xor_sync(0xffffffffu, l0, 2);
    l1 += __shfl_xor_sync(0xffffffffu, l1, 1);
    l1 += __shfl_xor_sync(0xffffffffu, l1, 2);
    float i0 = 1.0f / l0, i1 = 1.0f / l1;

    __half* o0 = out + ((size_t)(b * SS) + rg0) * DIM + h * HDIM + 2 * tg;
    __half* o1 = out + ((size_t)(b * SS) + rg1) * DIM + h * HDIM + 2 * tg;
    #pragma unroll
    for (int nb = 0; nb < 8; nb++) {
        *(__half2*)(o0 + nb * 8) = __floats2half2_rn(oacc[nb][0] * i0, oacc[nb][1] * i0);
        *(__half2*)(o1 + nb * 8) = __floats2half2_rn(oacc[nb][2] * i1, oacc[nb][3] * i1);
    }
}

// ---------------- launch ----------------
extern "C" void kernel_launch(void* const* d_in, const int* in_sizes, int n_in,
                              void* d_out, int out_size) {
    const float* x      = (const float*)d_in[0];
    const float* ln1_w  = (const float*)d_in[1];
    const float* ln1_b  = (const float*)d_in[2];
    const float* qkv_w  = (const float*)d_in[3];
    const float* qkv_b  = (const float*)d_in[4];
    const float* proj_w = (const float*)d_in[5];
    const float* proj_b = (const float*)d_in[6];
    const float* ln2_w  = (const float*)d_in[7];
    const float* ln2_b  = (const float*)d_in[8];
    const float* fc1_w  = (const float*)d_in[9];
    const float* fc1_b  = (const float*)d_in[10];
    const float* fc2_w  = (const float*)d_in[11];
    const float* fc2_b  = (const float*)d_in[12];
    float* out = (float*)d_out;

    __half *xn, *qkv, *attn, *hh, *qkvT, *projT, *fc1T, *fc2T;
    float *x1;
    cudaGetSymbolAddress((void**)&xn,    h_xn);
    cudaGetSymbolAddress((void**)&qkv,   h_qkv);
    cudaGetSymbolAddress((void**)&attn,  h_attn);
    cudaGetSymbolAddress((void**)&x1,    g_x1);
    cudaGetSymbolAddress((void**)&hh,    h_h);
    cudaGetSymbolAddress((void**)&qkvT,  h_qkvT);
    cudaGetSymbolAddress((void**)&projT, h_projT);
    cudaGetSymbolAddress((void**)&fc1T,  h_fc1T);
    cudaGetSymbolAddress((void**)&fc2T,  h_fc2T);

    static cudaStream_t s_tr = nullptr;
    static cudaEvent_t ev_fork = nullptr, ev_qkvT = nullptr, ev_wT = nullptr;
    if (!s_tr) {
        cudaStreamCreateWithFlags(&s_tr, cudaStreamNonBlocking);
        cudaEventCreateWithFlags(&ev_fork, cudaEventDisableTiming);
        cudaEventCreateWithFlags(&ev_qkvT, cudaEventDisableTiming);
        cudaEventCreateWithFlags(&ev_wT,   cudaEventDisableTiming);
    }

    // fork: weight transposes on side stream
    cudaEventRecord(ev_fork, 0);
    cudaStreamWaitEvent(s_tr, ev_fork, 0);
    transpose_h_kernel<<<dim3(3*DIM/32, DIM/32), 256, 0, s_tr>>>(qkv_w, qkvT, DIM, 3*DIM);
    cudaEventRecord(ev_qkvT, s_tr);
    transpose_h_kernel<<<dim3(DIM/32, DIM/32), 256, 0, s_tr>>>(proj_w, projT, DIM, DIM);
    transpose_h_kernel<<<dim3(MLP/32, DIM/32), 256, 0, s_tr>>>(fc1_w, fc1T, DIM, MLP);
    transpose_h_kernel<<<dim3(DIM/32, MLP/32), 256, 0, s_tr>>>(fc2_w, fc2T, MLP, DIM);
    cudaEventRecord(ev_wT, s_tr);

    // main stream
    ln_kernel<<<TT, 256>>>(x, ln1_w, ln1_b, xn);
    cudaStreamWaitEvent(0, ev_qkvT, 0);
    gemm_h<0><<<dim3(3*DIM/128, TT/128), 128>>>(TT, 3*DIM, DIM, xn, qkvT, qkv_b, nullptr, qkv);
    attn_mma<<<dim3(SS/128, BB*HEADS), 256>>>(qkv, attn);
    cudaStreamWaitEvent(0, ev_wT, 0);
    gemm_h<2><<<dim3(DIM/128, TT/128), 128>>>(TT, DIM, DIM, attn, projT, proj_b, x, x1);
    ln_kernel<<<TT, 256>>>(x1, ln2_w, ln2_b, xn);
    gemm_h<1><<<dim3(MLP/128, TT/128), 128>>>(TT, MLP, DIM, xn, fc1T, fc1_b, nullptr, hh);
    gemm_h<2><<<dim3(DIM/128, TT/128), 128>>>(TT, DIM, MLP, hh, fc2T, fc2_b, x1, out);
}

// round 15
// speedup vs baseline: 1.0023x; 1.0023x over previous
#include <cuda_runtime.h>
#include <cuda_fp16.h>
#include <math.h>
#include <stdint.h>

#define DIM   1024
#define HEADS 16
#define HDIM  64
#define MLP   4096
#define BB    4
#define SS    2048
#define TT    (BB*SS)   // 8192 tokens

// ---------------- scratch (device globals; no allocation) ----------------
__device__ __half h_xn[(size_t)TT*DIM];
__device__ __half h_qkv[(size_t)TT*3*DIM];
__device__ __half h_attn[(size_t)TT*DIM];
__device__ float  g_x1[(size_t)TT*DIM];
__device__ __half h_h[(size_t)TT*MLP];
__device__ __half h_qkvT[(size_t)3*DIM*DIM];
__device__ __half h_projT[(size_t)DIM*DIM];
__device__ __half h_fc1T[(size_t)DIM*MLP];
__device__ __half h_fc2T[(size_t)MLP*DIM];

// ---------------- ptx helpers ----------------
__device__ __forceinline__ void mma_f16(float* c, const uint32_t* a, const uint32_t* b) {
    asm volatile(
        "mma.sync.aligned.m16n8k16.row.col.f32.f16.f16.f32 "
        "{%0,%1,%2,%3}, {%4,%5,%6,%7}, {%8,%9}, {%0,%1,%2,%3};"
        : "+f"(c[0]), "+f"(c[1]), "+f"(c[2]), "+f"(c[3])
        : "r"(a[0]), "r"(a[1]), "r"(a[2]), "r"(a[3]), "r"(b[0]), "r"(b[1]));
}

__device__ __forceinline__ void ldmx4(uint32_t& r0, uint32_t& r1, uint32_t& r2, uint32_t& r3,
                                      const __half* p) {
    uint32_t a = (uint32_t)__cvta_generic_to_shared((void*)p);
    asm volatile("ldmatrix.sync.aligned.m8n8.x4.shared.b16 {%0,%1,%2,%3}, [%4];"
                 : "=r"(r0), "=r"(r1), "=r"(r2), "=r"(r3) : "r"(a));
}

__device__ __forceinline__ void ldmx4t(uint32_t& r0, uint32_t& r1, uint32_t& r2, uint32_t& r3,
                                       const __half* p) {
    uint32_t a = (uint32_t)__cvta_generic_to_shared((void*)p);
    asm volatile("ldmatrix.sync.aligned.m8n8.x4.trans.shared.b16 {%0,%1,%2,%3}, [%4];"
                 : "=r"(r0), "=r"(r1), "=r"(r2), "=r"(r3) : "r"(a));
}

__device__ __forceinline__ void cpa16(__half* dst, const __half* src) {
    uint32_t s = (uint32_t)__cvta_generic_to_shared((void*)dst);
    asm volatile("cp.async.cg.shared.global [%0], [%1], 16;" :: "r"(s), "l"(src));
}
#define CP_COMMIT() asm volatile("cp.async.commit_group;" ::: "memory")
#define CP_WAIT2()  asm volatile("cp.async.wait_group 2;" ::: "memory")
#define CP_WAIT1()  asm volatile("cp.async.wait_group 1;" ::: "memory")

__device__ __forceinline__ float ex2f(float x) {
    float r;
    asm("ex2.approx.f32 %0, %1;" : "=f"(r) : "f"(x));
    return r;
}

// ---------------- LayerNorm: fp32 in -> fp16 out ----------------
__global__ __launch_bounds__(256)
void ln_kernel(const float* __restrict__ x, const float* __restrict__ w,
               const float* __restrict__ b, __half* __restrict__ out) {
    int row = blockIdx.x;
    int tid = threadIdx.x;
    const float4* xr = (const float4*)(x + (size_t)row * DIM);
    float4 v = xr[tid];
    float s  = v.x + v.y + v.z + v.w;
    float ss = v.x*v.x + v.y*v.y + v.z*v.z + v.w*v.w;
    #pragma unroll
    for (int o = 16; o; o >>= 1) {
        s  += __shfl_xor_sync(0xffffffffu, s,  o);
        ss += __shfl_xor_sync(0xffffffffu, ss, o);
    }
    __shared__ float red0[8], red1[8];
    int wid = tid >> 5, lid = tid & 31;
    if (lid == 0) { red0[wid] = s; red1[wid] = ss; }
    __syncthreads();
    float sum = 0.f, sumsq = 0.f;
    #pragma unroll
    for (int i = 0; i < 8; i++) { sum += red0[i]; sumsq += red1[i]; }
    float mu   = sum * (1.0f / DIM);
    float var  = sumsq * (1.0f / DIM) - mu * mu;
    float rstd = rsqrtf(var + 1e-5f);
    float4 wv = ((const float4*)w)[tid];
    float4 bv = ((const float4*)b)[tid];
    __half2* o2 = (__half2*)(out + (size_t)row * DIM);
    o2[tid*2+0] = __floats2half2_rn((v.x - mu)*rstd*wv.x + bv.x,
                                    (v.y - mu)*rstd*wv.y + bv.y);
    o2[tid*2+1] = __floats2half2_rn((v.z - mu)*rstd*wv.z + bv.z,
                                    (v.w - mu)*rstd*wv.w + bv.w);
}

// ---------------- weight transpose [K,N] fp32 -> [N,K] fp16 ----------------
__global__ __launch_bounds__(256)
void transpose_h_kernel(const float* __restrict__ in, __half* __restrict__ out,
                        int K, int N) {
    __shared__ float tile[32][33];
    int bx = blockIdx.x;
    int by = blockIdx.y;
    int tx = threadIdx.x & 31;
    int ty = threadIdx.x >> 5;
    #pragma unroll
    for (int i = 0; i < 32; i += 8)
        tile[ty + i][tx] = in[(size_t)(by * 32 + ty + i) * N + bx * 32 + tx];
    __syncthreads();
    #pragma unroll
    for (int i = 0; i < 32; i += 8)
        out[(size_t)(bx * 32 + ty + i) * K + by * 32 + tx] = __float2half_rn(tile[tx][ty + i]);
}

// ---------------- fp16 mma GEMM, 4-stage cp.async + ldmatrix, 1 sync/chunk ----------------
#define GLDA 40
#define STG_H (2 * 128 * GLDA)

template <int EPI>
__global__ __launch_bounds__(128, 2)
void gemm_h(int M, int N, int K,
            const __half* __restrict__ A, const __half* __restrict__ Bt,
            const float* __restrict__ bias, const float* __restrict__ R,
            void* __restrict__ Cout) {
    __shared__ __half sh[4 * STG_H];

    int tid = threadIdx.x;
    int wid = tid >> 5, lane = tid & 31;
    int gid = lane >> 2, tg = lane & 3;
    int wm = wid & 1, wn = wid >> 1;
    int bx = blockIdx.x, by = blockIdx.y;

    const __half* Ab = A  + (size_t)(by * 128) * K;
    const __half* Bb = Bt + (size_t)(bx * 128) * K;

    float acc[4][8][4];
    #pragma unroll
    for (int i = 0; i < 4; i++)
        #pragma unroll
        for (int j = 0; j < 8; j++)
            #pragma unroll
            for (int c = 0; c < 4; c++) acc[i][j][c] = 0.f;

    int NC = K / 32;

    auto issue = [&](int s) {
        if (s < NC) {
            __half* sa = sh + (s & 3) * STG_H;
            __half* sb = sa + 128 * GLDA;
            int kb = s * 32;
            #pragma unroll
            for (int it = 0; it < 4; it++) {
                int idx = it * 128 + tid;
                int r = idx >> 2, c8 = (idx & 3) * 8;
                cpa16(sa + r * GLDA + c8, Ab + (size_t)r * K + kb + c8);
                cpa16(sb + r * GLDA + c8, Bb + (size_t)r * K + kb + c8);
            }
        }
        CP_COMMIT();
    };

    issue(0); issue(1); issue(2);

    for (int kc = 0; kc < NC; kc++) {
        CP_WAIT2();
        __syncthreads();
        issue(kc + 3);   // refills buffer (kc-1)&3: all warps past compute(kc-1)

        const __half* Ac = sh + (kc & 3) * STG_H;
        const __half* Bc = Ac + 128 * GLDA;

        #pragma unroll
        for (int kk = 0; kk < 32; kk += 16) {
            uint32_t af[4][4];
            #pragma unroll
            for (int mf = 0; mf < 4; mf++) {
                const __half* p = Ac + (wm * 64 + mf * 16 + (lane & 15)) * GLDA
                                  + kk + (lane >> 4) * 8;
                ldmx4(af[mf][0], af[mf][1], af[mf][2], af[mf][3], p);
            }
            uint32_t bf[8][2];
            #pragma unroll
            for (int pj = 0; pj < 4; pj++) {
                const __half* p = Bc + (wn * 64 + (pj * 2 + (lane >> 4)) * 8 + (lane & 7)) * GLDA
                                  + kk + ((lane >> 3) & 1) * 8;
                ldmx4(bf[2*pj][0], bf[2*pj][1], bf[2*pj+1][0], bf[2*pj+1][1], p);
            }
            #pragma unroll
            for (int mf = 0; mf < 4; mf++)
                #pragma unroll
                for (int nb = 0; nb < 8; nb++)
                    mma_f16(acc[mf][nb], af[mf], bf[nb]);
        }
    }

    // epilogue
    int colW = bx * 128 + wn * 64;
    #pragma unroll
    for (int mf = 0; mf < 4; mf++) {
        #pragma unroll
        for (int r2 = 0; r2 < 2; r2++) {
            int row = by * 128 + wm * 64 + mf * 16 + gid + r2 * 8;
            #pragma unroll
            for (int nb = 0; nb < 8; nb++) {
                int gcol = colW + nb * 8 + 2 * tg;
                float t0 = acc[mf][nb][r2 * 2 + 0] + bias[gcol];
                float t1 = acc[mf][nb][r2 * 2 + 1] + bias[gcol + 1];
                if (EPI == 1) {
                    t0 = 0.5f * t0 * (1.0f + erff(t0 * 0.70710678118654752f));
                    t1 = 0.5f * t1 * (1.0f + erff(t1 * 0.70710678118654752f));
                }
                if (EPI == 2) {
                    float2 rv = *(const float2*)(R + (size_t)row * N + gcol);
                    t0 += rv.x; t1 += rv.y;
                    *(float2*)((float*)Cout + (size_t)row * N + gcol) = make_float2(t0, t1);
                } else {
                    *(__half2*)((__half*)Cout + (size_t)row * N + gcol) = __floats2half2_rn(t0, t1);
                }
            }
        }
    }
}

// ---------------- causal flash attention: 128 q/CTA, 8 warps, log2-domain softmax ----------------
#define KLD 72
#define ATILE (64 * KLD)

__global__ __launch_bounds__(256)
void attn_mma(const __half* __restrict__ qkv, __half* __restrict__ out) {
    int qt = blockIdx.x, bh = blockIdx.y;     // qt: 0..15 (128-query tiles)
    int b = bh >> 4, h = bh & 15;
    int tid = threadIdx.x;
    int wid = tid >> 5, lane = tid & 31;
    int gid = lane >> 2, tg = lane & 3;
    int q0 = qt * 128;
    int ntiles = 2 * qt + 2;

    __shared__ __half Ks3[3 * ATILE];   // [key][dim]
    __shared__ __half Vs3[3 * ATILE];   // [key][dim]

    auto issueA = [&](int s) {
        if (s < ntiles) {
            __half* ka = Ks3 + (s % 3) * ATILE;
            __half* va = Vs3 + (s % 3) * ATILE;
            #pragma unroll
            for (int it = 0; it < 2; it++) {
                int idx = it * 256 + tid;
                int r = idx >> 3, c8 = (idx & 7) * 8;
                const __half* src = qkv + ((size_t)(b * SS) + s * 64 + r) * (3 * DIM) + h * HDIM + c8;
                cpa16(ka + r * KLD + c8, src + DIM);
                cpa16(va + r * KLD + c8, src + 2 * DIM);
            }
        }
        CP_COMMIT();
    };

    uint32_t qa[4][4];
    {
        const __half* Q0 = qkv + ((size_t)(b * SS) + q0 + wid * 16 + gid) * (3 * DIM) + h * HDIM + 2 * tg;
        const __half* Q1 = Q0 + (size_t)8 * (3 * DIM);
        #pragma unroll
        for (int kcc = 0; kcc < 4; kcc++) {
            qa[kcc][0] = *(const uint32_t*)(Q0 + kcc * 16);
            qa[kcc][1] = *(const uint32_t*)(Q1 + kcc * 16);
            qa[kcc][2] = *(const uint32_t*)(Q0 + kcc * 16 + 8);
            qa[kcc][3] = *(const uint32_t*)(Q1 + kcc * 16 + 8);
        }
    }

    issueA(0); issueA(1);

    float oacc[8][4];
    #pragma unroll
    for (int nb = 0; nb < 8; nb++)
        #pragma unroll
        for (int c = 0; c < 4; c++) oacc[nb][c] = 0.f;
    float m0 = -1e30f, m1 = -1e30f, l0 = 0.f, l1 = 0.f;
    int rg0 = q0 + wid * 16 + gid;
    int rg1 = rg0 + 8;

    int lm_row = ((lane >> 4)) * 8 + (lane & 7);
    int lm_koff = ((lane >> 3) & 1) * 8;
    int vt_row = (lane & 7) + ((lane >> 3) & 1) * 8;
    int vt_col = (lane >> 4) * 8;

    // score scale in log2 domain: 0.125 * log2(e)
    const float sc = 0.125f * 1.44269504088896340736f;

    // one tile step; MASK chosen per phase (compile-time)
    auto tile_step = [&](int jt, bool need_mask) {
        CP_WAIT1();
        __syncthreads();
        issueA(jt + 2);

        const __half* Kc = Ks3 + (jt % 3) * ATILE;
        const __half* Vc = Vs3 + (jt % 3) * ATILE;

        // S = Q @ K^T
        float sacc[8][4];
        #pragma unroll
        for (int nb = 0; nb < 8; nb++)
            #pragma unroll
            for (int c = 0; c < 4; c++) sacc[nb][c] = 0.f;
        #pragma unroll
        for (int kcc = 0; kcc < 4; kcc++) {
            uint32_t bf[8][2];
            #pragma unroll
            for (int pj = 0; pj < 4; pj++) {
                const __half* p = Kc + (pj * 16 + lm_row) * KLD + kcc * 16 + lm_koff;
                ldmx4(bf[2*pj][0], bf[2*pj][1], bf[2*pj+1][0], bf[2*pj+1][1], p);
            }
            #pragma unroll
            for (int nb = 0; nb < 8; nb++)
                mma_f16(sacc[nb], qa[kcc], bf[nb]);
        }

        float tm0 = -1e30f, tm1 = -1e30f;
        #pragma unroll
        for (int nb = 0; nb < 8; nb++) {
            float s0 = sacc[nb][0] * sc, s1 = sacc[nb][1] * sc;
            float s2 = sacc[nb][2] * sc, s3 = sacc[nb][3] * sc;
            if (need_mask) {
                int col = jt * 64 + nb * 8 + 2 * tg;
                if (col     > rg0) s0 = -1e30f;
                if (col + 1 > rg0) s1 = -1e30f;
                if (col     > rg1) s2 = -1e30f;
                if (col + 1 > rg1) s3 = -1e30f;
            }
            sacc[nb][0] = s0; sacc[nb][1] = s1; sacc[nb][2] = s2; sacc[nb][3] = s3;
            tm0 = fmaxf(tm0, fmaxf(s0, s1));
            tm1 = fmaxf(tm1, fmaxf(s2, s3));
        }
        tm0 = fmaxf(tm0, __shfl_xor_sync(0xffffffffu, tm0, 1));
        tm0 = fmaxf(tm0, __shfl_xor_sync(0xffffffffu, tm0, 2));
        tm1 = fmaxf(tm1, __shfl_xor_sync(0xffffffffu, tm1, 1));
        tm1 = fmaxf(tm1, __shfl_xor_sync(0xffffffffu, tm1, 2));

        float mn0 = fmaxf(m0, tm0), mn1 = fmaxf(m1, tm1);
        float cr0 = ex2f(m0 - mn0), cr1 = ex2f(m1 - mn1);
        l0 *= cr0; l1 *= cr1;
        #pragma unroll
        for (int nb = 0; nb < 8; nb++) {
            oacc[nb][0] *= cr0; oacc[nb][1] *= cr0;
            oacc[nb][2] *= cr1; oacc[nb][3] *= cr1;
        }
        uint32_t pa01[8], pa23[8];
        #pragma unroll
        for (int nb = 0; nb < 8; nb++) {
            float p0 = ex2f(sacc[nb][0] - mn0);
            float p1 = ex2f(sacc[nb][1] - mn0);
            float p2 = ex2f(sacc[nb][2] - mn1);
            float p3 = ex2f(sacc[nb][3] - mn1);
            l0 += p0 + p1; l1 += p2 + p3;
            __half2 h01 = __floats2half2_rn(p0, p1);
            __half2 h23 = __floats2half2_rn(p2, p3);
            pa01[nb] = *(uint32_t*)&h01;
            pa23[nb] = *(uint32_t*)&h23;
        }
        m0 = mn0; m1 = mn1;

        // O += P @ V
        #pragma unroll
        for (int kcc = 0; kcc < 4; kcc++) {
            uint32_t aa[4] = { pa01[2*kcc], pa23[2*kcc], pa01[2*kcc+1], pa23[2*kcc+1] };
            uint32_t bf[8][2];
            #pragma unroll
            for (int pj = 0; pj < 4; pj++) {
                const __half* p = Vc + (kcc * 16 + vt_row) * KLD + pj * 16 + vt_col;
                ldmx4t(bf[2*pj][0], bf[2*pj][1], bf[2*pj+1][0], bf[2*pj+1][1], p);
            }
            #pragma unroll
            for (int nb = 0; nb < 8; nb++)
                mma_f16(oacc[nb], aa, bf[nb]);
        }
    };

    // phase 1: mask-free tiles
    for (int jt = 0; jt < 2 * qt; jt++) tile_step(jt, false);
    // phase 2: the two diagonal (masked) tiles
    tile_step(2 * qt, true);
    tile_step(2 * qt + 1, true);

    l0 += __shfl_xor_sync(0xffffffffu, l0, 1);
    l0 += __shfl_xor_sync(0xffffffffu, l0, 2);
    l1 += __shfl_xor_sync(0xffffffffu, l1, 1);
    l1 += __shfl_xor_sync(0xffffffffu, l1, 2);
    float i0 = 1.0f / l0, i1 = 1.0f / l1;

    __half* o0 = out + ((size_t)(b * SS) + rg0) * DIM + h * HDIM + 2 * tg;
    __half* o1 = out + ((size_t)(b * SS) + rg1) * DIM + h * HDIM + 2 * tg;
    #pragma unroll
    for (int nb = 0; nb < 8; nb++) {
        *(__half2*)(o0 + nb * 8) = __floats2half2_rn(oacc[nb][0] * i0, oacc[nb][1] * i0);
        *(__half2*)(o1 + nb * 8) = __floats2half2_rn(oacc[nb][2] * i1, oacc[nb][3] * i1);
    }
}

// ---------------- launch ----------------
extern "C" void kernel_launch(void* const* d_in, const int* in_sizes, int n_in,
                              void* d_out, int out_size) {
    const float* x      = (const float*)d_in[0];
    const float* ln1_w  = (const float*)d_in[1];
    const float* ln1_b  = (const float*)d_in[2];
    const float* qkv_w  = (const float*)d_in[3];
    const float* qkv_b  = (const float*)d_in[4];
    const float* proj_w = (const float*)d_in[5];
    const float* proj_b = (const float*)d_in[6];
    const float* ln2_w  = (const float*)d_in[7];
    const float* ln2_b  = (const float*)d_in[8];
    const float* fc1_w  = (const float*)d_in[9];
    const float* fc1_b  = (const float*)d_in[10];
    const float* fc2_w  = (const float*)d_in[11];
    const float* fc2_b  = (const float*)d_in[12];
    float* out = (float*)d_out;

    __half *xn, *qkv, *attn, *hh, *qkvT, *projT, *fc1T, *fc2T;
    float *x1;
    cudaGetSymbolAddress((void**)&xn,    h_xn);
    cudaGetSymbolAddress((void**)&qkv,   h_qkv);
    cudaGetSymbolAddress((void**)&attn,  h_attn);
    cudaGetSymbolAddress((void**)&x1,    g_x1);
    cudaGetSymbolAddress((void**)&hh,    h_h);
    cudaGetSymbolAddress((void**)&qkvT,  h_qkvT);
    cudaGetSymbolAddress((void**)&projT, h_projT);
    cudaGetSymbolAddress((void**)&fc1T,  h_fc1T);
    cudaGetSymbolAddress((void**)&fc2T,  h_fc2T);

    static cudaStream_t s_tr = nullptr;
    static cudaEvent_t ev_fork = nullptr, ev_qkvT = nullptr, ev_wT = nullptr;
    if (!s_tr) {
        cudaStreamCreateWithFlags(&s_tr, cudaStreamNonBlocking);
        cudaEventCreateWithFlags(&ev_fork, cudaEventDisableTiming);
        cudaEventCreateWithFlags(&ev_qkvT, cudaEventDisableTiming);
        cudaEventCreateWithFlags(&ev_wT,   cudaEventDisableTiming);
    }

    // fork: weight transposes on side stream
    cudaEventRecord(ev_fork, 0);
    cudaStreamWaitEvent(s_tr, ev_fork, 0);
    transpose_h_kernel<<<dim3(3*DIM/32, DIM/32), 256, 0, s_tr>>>(qkv_w, qkvT, DIM, 3*DIM);
    cudaEventRecord(ev_qkvT, s_tr);
    transpose_h_kernel<<<dim3(DIM/32, DIM/32), 256, 0, s_tr>>>(proj_w, projT, DIM, DIM);
    transpose_h_kernel<<<dim3(MLP/32, DIM/32), 256, 0, s_tr>>>(fc1_w, fc1T, DIM, MLP);
    transpose_h_kernel<<<dim3(DIM/32, MLP/32), 256, 0, s_tr>>>(fc2_w, fc2T, MLP, DIM);
    cudaEventRecord(ev_wT, s_tr);

    // main stream
    ln_kernel<<<TT, 256>>>(x, ln1_w, ln1_b, xn);
    cudaStreamWaitEvent(0, ev_qkvT, 0);
    gemm_h<0><<<dim3(3*DIM/128, TT/128), 128>>>(TT, 3*DIM, DIM, xn, qkvT, qkv_b, nullptr, qkv);
    attn_mma<<<dim3(SS/128, BB*HEADS), 256>>>(qkv, attn);
    cudaStreamWaitEvent(0, ev_wT, 0);
    gemm_h<2><<<dim3(DIM/128, TT/128), 128>>>(TT, DIM, DIM, attn, projT, proj_b, x, x1);
    ln_kernel<<<TT, 256>>>(x1, ln2_w, ln2_b, xn);
    gemm_h<1><<<dim3(MLP/128, TT/128), 128>>>(TT, MLP, DIM, xn, fc1T, fc1_b, nullptr, hh);
    gemm_h<2><<<dim3(DIM/128, TT/128), 128>>>(TT, DIM, MLP, hh, fc2T, fc2_b, x1, out);
}

// round 16
// speedup vs baseline: 1.0183x; 1.0159x over previous
#include <cuda_runtime.h>
#include <cuda_fp16.h>
#include <math.h>
#include <stdint.h>

#define DIM   1024
#define HEADS 16
#define HDIM  64
#define MLP   4096
#define BB    4
#define SS    2048
#define TT    (BB*SS)   // 8192 tokens

// ---------------- scratch (device globals; no allocation) ----------------
__device__ __half h_xn[(size_t)TT*DIM];
__device__ __half h_qkv[(size_t)TT*3*DIM];
__device__ __half h_attn[(size_t)TT*DIM];
__device__ float  g_x1[(size_t)TT*DIM];
__device__ __half h_h[(size_t)TT*MLP];
__device__ __half h_qkvT[(size_t)3*DIM*DIM];
__device__ __half h_projT[(size_t)DIM*DIM];
__device__ __half h_fc1T[(size_t)DIM*MLP];
__device__ __half h_fc2T[(size_t)MLP*DIM];

// ---------------- ptx helpers ----------------
__device__ __forceinline__ void mma_f16(float* c, const uint32_t* a, const uint32_t* b) {
    asm volatile(
        "mma.sync.aligned.m16n8k16.row.col.f32.f16.f16.f32 "
        "{%0,%1,%2,%3}, {%4,%5,%6,%7}, {%8,%9}, {%0,%1,%2,%3};"
        : "+f"(c[0]), "+f"(c[1]), "+f"(c[2]), "+f"(c[3])
        : "r"(a[0]), "r"(a[1]), "r"(a[2]), "r"(a[3]), "r"(b[0]), "r"(b[1]));
}

__device__ __forceinline__ void ldmx4(uint32_t& r0, uint32_t& r1, uint32_t& r2, uint32_t& r3,
                                      const __half* p) {
    uint32_t a = (uint32_t)__cvta_generic_to_shared((void*)p);
    asm volatile("ldmatrix.sync.aligned.m8n8.x4.shared.b16 {%0,%1,%2,%3}, [%4];"
                 : "=r"(r0), "=r"(r1), "=r"(r2), "=r"(r3) : "r"(a));
}

__device__ __forceinline__ void ldmx4t(uint32_t& r0, uint32_t& r1, uint32_t& r2, uint32_t& r3,
                                       const __half* p) {
    uint32_t a = (uint32_t)__cvta_generic_to_shared((void*)p);
    asm volatile("ldmatrix.sync.aligned.m8n8.x4.trans.shared.b16 {%0,%1,%2,%3}, [%4];"
                 : "=r"(r0), "=r"(r1), "=r"(r2), "=r"(r3) : "r"(a));
}

__device__ __forceinline__ void cpa16(__half* dst, const __half* src) {
    uint32_t s = (uint32_t)__cvta_generic_to_shared((void*)dst);
    asm volatile("cp.async.cg.shared.global [%0], [%1], 16;" :: "r"(s), "l"(src));
}
#define CP_COMMIT() asm volatile("cp.async.commit_group;" ::: "memory")
#define CP_WAIT2()  asm volatile("cp.async.wait_group 2;" ::: "memory")
#define CP_WAIT1()  asm volatile("cp.async.wait_group 1;" ::: "memory")

// ---------------- LayerNorm: fp32 in -> fp16 out ----------------
__global__ __launch_bounds__(256)
void ln_kernel(const float* __restrict__ x, const float* __restrict__ w,
               const float* __restrict__ b, __half* __restrict__ out) {
    int row = blockIdx.x;
    int tid = threadIdx.x;
    const float4* xr = (const float4*)(x + (size_t)row * DIM);
    float4 v = xr[tid];
    float s  = v.x + v.y + v.z + v.w;
    float ss = v.x*v.x + v.y*v.y + v.z*v.z + v.w*v.w;
    #pragma unroll
    for (int o = 16; o; o >>= 1) {
        s  += __shfl_xor_sync(0xffffffffu, s,  o);
        ss += __shfl_xor_sync(0xffffffffu, ss, o);
    }
    __shared__ float red0[8], red1[8];
    int wid = tid >> 5, lid = tid & 31;
    if (lid == 0) { red0[wid] = s; red1[wid] = ss; }
    __syncthreads();
    float sum = 0.f, sumsq = 0.f;
    #pragma unroll
    for (int i = 0; i < 8; i++) { sum += red0[i]; sumsq += red1[i]; }
    float mu   = sum * (1.0f / DIM);
    float var  = sumsq * (1.0f / DIM) - mu * mu;
    float rstd = rsqrtf(var + 1e-5f);
    float4 wv = ((const float4*)w)[tid];
    float4 bv = ((const float4*)b)[tid];
    __half2* o2 = (__half2*)(out + (size_t)row * DIM);
    o2[tid*2+0] = __floats2half2_rn((v.x - mu)*rstd*wv.x + bv.x,
                                    (v.y - mu)*rstd*wv.y + bv.y);
    o2[tid*2+1] = __floats2half2_rn((v.z - mu)*rstd*wv.z + bv.z,
                                    (v.w - mu)*rstd*wv.w + bv.w);
}

// ---------------- weight transpose [K,N] fp32 -> [N,K] fp16 ----------------
__global__ __launch_bounds__(256)
void transpose_h_kernel(const float* __restrict__ in, __half* __restrict__ out,
                        int K, int N) {
    __shared__ float tile[32][33];
    int bx = blockIdx.x;
    int by = blockIdx.y;
    int tx = threadIdx.x & 31;
    int ty = threadIdx.x >> 5;
    #pragma unroll
    for (int i = 0; i < 32; i += 8)
        tile[ty + i][tx] = in[(size_t)(by * 32 + ty + i) * N + bx * 32 + tx];
    __syncthreads();
    #pragma unroll
    for (int i = 0; i < 32; i += 8)
        out[(size_t)(bx * 32 + ty + i) * K + by * 32 + tx] = __float2half_rn(tile[tx][ty + i]);
}

// ---------------- fp16 mma GEMM, 4-stage cp.async + ldmatrix, 1 sync/chunk ----------------
#define GLDA 40
#define STG_H (2 * 128 * GLDA)

template <int EPI>
__global__ __launch_bounds__(128, 2)
void gemm_h(int M, int N, int K,
            const __half* __restrict__ A, const __half* __restrict__ Bt,
            const float* __restrict__ bias, const float* __restrict__ R,
            void* __restrict__ Cout) {
    __shared__ __half sh[4 * STG_H];

    int tid = threadIdx.x;
    int wid = tid >> 5, lane = tid & 31;
    int gid = lane >> 2, tg = lane & 3;
    int wm = wid & 1, wn = wid >> 1;
    int bx = blockIdx.x, by = blockIdx.y;

    const __half* Ab = A  + (size_t)(by * 128) * K;
    const __half* Bb = Bt + (size_t)(bx * 128) * K;

    float acc[4][8][4];
    #pragma unroll
    for (int i = 0; i < 4; i++)
        #pragma unroll
        for (int j = 0; j < 8; j++)
            #pragma unroll
            for (int c = 0; c < 4; c++) acc[i][j][c] = 0.f;

    int NC = K / 32;

    auto issue = [&](int s) {
        if (s < NC) {
            __half* sa = sh + (s & 3) * STG_H;
            __half* sb = sa + 128 * GLDA;
            int kb = s * 32;
            #pragma unroll
            for (int it = 0; it < 4; it++) {
                int idx = it * 128 + tid;
                int r = idx >> 2, c8 = (idx & 3) * 8;
                cpa16(sa + r * GLDA + c8, Ab + (size_t)r * K + kb + c8);
                cpa16(sb + r * GLDA + c8, Bb + (size_t)r * K + kb + c8);
            }
        }
        CP_COMMIT();
    };

    issue(0); issue(1); issue(2);

    for (int kc = 0; kc < NC; kc++) {
        CP_WAIT2();
        __syncthreads();
        issue(kc + 3);   // refills buffer (kc-1)&3: all warps past compute(kc-1)

        const __half* Ac = sh + (kc & 3) * STG_H;
        const __half* Bc = Ac + 128 * GLDA;

        #pragma unroll
        for (int kk = 0; kk < 32; kk += 16) {
            uint32_t af[4][4];
            #pragma unroll
            for (int mf = 0; mf < 4; mf++) {
                const __half* p = Ac + (wm * 64 + mf * 16 + (lane & 15)) * GLDA
                                  + kk + (lane >> 4) * 8;
                ldmx4(af[mf][0], af[mf][1], af[mf][2], af[mf][3], p);
            }
            uint32_t bf[8][2];
            #pragma unroll
            for (int pj = 0; pj < 4; pj++) {
                const __half* p = Bc + (wn * 64 + (pj * 2 + (lane >> 4)) * 8 + (lane & 7)) * GLDA
                                  + kk + ((lane >> 3) & 1) * 8;
                ldmx4(bf[2*pj][0], bf[2*pj][1], bf[2*pj+1][0], bf[2*pj+1][1], p);
            }
            #pragma unroll
            for (int mf = 0; mf < 4; mf++)
                #pragma unroll
                for (int nb = 0; nb < 8; nb++)
                    mma_f16(acc[mf][nb], af[mf], bf[nb]);
        }
    }

    // epilogue
    int colW = bx * 128 + wn * 64;
    #pragma unroll
    for (int mf = 0; mf < 4; mf++) {
        #pragma unroll
        for (int r2 = 0; r2 < 2; r2++) {
            int row = by * 128 + wm * 64 + mf * 16 + gid + r2 * 8;
            #pragma unroll
            for (int nb = 0; nb < 8; nb++) {
                int gcol = colW + nb * 8 + 2 * tg;
                float t0 = acc[mf][nb][r2 * 2 + 0] + bias[gcol];
                float t1 = acc[mf][nb][r2 * 2 + 1] + bias[gcol + 1];
                if (EPI == 1) {
                    t0 = 0.5f * t0 * (1.0f + erff(t0 * 0.70710678118654752f));
                    t1 = 0.5f * t1 * (1.0f + erff(t1 * 0.70710678118654752f));
                }
                if (EPI == 2) {
                    float2 rv = *(const float2*)(R + (size_t)row * N + gcol);
                    t0 += rv.x; t1 += rv.y;
                    *(float2*)((float*)Cout + (size_t)row * N + gcol) = make_float2(t0, t1);
                } else {
                    *(__half2*)((__half*)Cout + (size_t)row * N + gcol) = __floats2half2_rn(t0, t1);
                }
            }
        }
    }
}

// ---------------- causal flash attention: paired q-tiles for uniform CTA work ----------------
// grid (8, B*H): CTA bx handles q-tiles bx and 15-bx => every CTA does exactly 36 tile-steps.
#define KLD 72
#define ATILE (64 * KLD)

__global__ __launch_bounds__(256)
void attn_mma(const __half* __restrict__ qkv, __half* __restrict__ out) {
    int bh = blockIdx.y;
    int b = bh >> 4, h = bh & 15;
    int tid = threadIdx.x;
    int wid = tid >> 5, lane = tid & 31;
    int gid = lane >> 2, tg = lane & 3;

    __shared__ __half Ks3[3 * ATILE];   // [key][dim]
    __shared__ __half Vs3[3 * ATILE];   // [key][dim]

    int lm_row = ((lane >> 4)) * 8 + (lane & 7);
    int lm_koff = ((lane >> 3) & 1) * 8;
    int vt_row = (lane & 7) + ((lane >> 3) & 1) * 8;
    int vt_col = (lane >> 4) * 8;

    #pragma unroll 1
    for (int half = 0; half < 2; half++) {
        int qt = half ? (15 - blockIdx.x) : blockIdx.x;
        int q0 = qt * 128;
        int ntiles = 2 * qt + 2;

        auto issueA = [&](int s) {
            if (s < ntiles) {
                __half* ka = Ks3 + (s % 3) * ATILE;
                __half* va = Vs3 + (s % 3) * ATILE;
                #pragma unroll
                for (int it = 0; it < 2; it++) {
                    int idx = it * 256 + tid;
                    int r = idx >> 3, c8 = (idx & 7) * 8;
                    const __half* src = qkv + ((size_t)(b * SS) + s * 64 + r) * (3 * DIM) + h * HDIM + c8;
                    cpa16(ka + r * KLD + c8, src + DIM);
                    cpa16(va + r * KLD + c8, src + 2 * DIM);
                }
            }
            CP_COMMIT();
        };

        uint32_t qa[4][4];
        {
            const __half* Q0 = qkv + ((size_t)(b * SS) + q0 + wid * 16 + gid) * (3 * DIM) + h * HDIM + 2 * tg;
            const __half* Q1 = Q0 + (size_t)8 * (3 * DIM);
            #pragma unroll
            for (int kcc = 0; kcc < 4; kcc++) {
                qa[kcc][0] = *(const uint32_t*)(Q0 + kcc * 16);
                qa[kcc][1] = *(const uint32_t*)(Q1 + kcc * 16);
                qa[kcc][2] = *(const uint32_t*)(Q0 + kcc * 16 + 8);
                qa[kcc][3] = *(const uint32_t*)(Q1 + kcc * 16 + 8);
            }
        }

        issueA(0); issueA(1);

        float oacc[8][4];
        #pragma unroll
        for (int nb = 0; nb < 8; nb++)
            #pragma unroll
            for (int c = 0; c < 4; c++) oacc[nb][c] = 0.f;
        float m0 = -1e30f, m1 = -1e30f, l0 = 0.f, l1 = 0.f;
        int rg0 = q0 + wid * 16 + gid;
        int rg1 = rg0 + 8;

        for (int jt = 0; jt < ntiles; jt++) {
            CP_WAIT1();
            __syncthreads();
            issueA(jt + 2);

            const __half* Kc = Ks3 + (jt % 3) * ATILE;
            const __half* Vc = Vs3 + (jt % 3) * ATILE;

            // S = Q @ K^T
            float sacc[8][4];
            #pragma unroll
            for (int nb = 0; nb < 8; nb++)
                #pragma unroll
                for (int c = 0; c < 4; c++) sacc[nb][c] = 0.f;
            #pragma unroll
            for (int kcc = 0; kcc < 4; kcc++) {
                uint32_t bf[8][2];
                #pragma unroll
                for (int pj = 0; pj < 4; pj++) {
                    const __half* p = Kc + (pj * 16 + lm_row) * KLD + kcc * 16 + lm_koff;
                    ldmx4(bf[2*pj][0], bf[2*pj][1], bf[2*pj+1][0], bf[2*pj+1][1], p);
                }
                #pragma unroll
                for (int nb = 0; nb < 8; nb++)
                    mma_f16(sacc[nb], qa[kcc], bf[nb]);
            }

            const float sc = 0.125f;
            float tm0 = -1e30f, tm1 = -1e30f;
            bool need_mask = (jt >= 2 * qt);
            #pragma unroll
            for (int nb = 0; nb < 8; nb++) {
                int col = jt * 64 + nb * 8 + 2 * tg;
                float s0 = sacc[nb][0] * sc, s1 = sacc[nb][1] * sc;
                float s2 = sacc[nb][2] * sc, s3 = sacc[nb][3] * sc;
                if (need_mask) {
                    if (col     > rg0) s0 = -1e30f;
                    if (col + 1 > rg0) s1 = -1e30f;
                    if (col     > rg1) s2 = -1e30f;
                    if (col + 1 > rg1) s3 = -1e30f;
                }
                sacc[nb][0] = s0; sacc[nb][1] = s1; sacc[nb][2] = s2; sacc[nb][3] = s3;
                tm0 = fmaxf(tm0, fmaxf(s0, s1));
                tm1 = fmaxf(tm1, fmaxf(s2, s3));
            }
            tm0 = fmaxf(tm0, __shfl_xor_sync(0xffffffffu, tm0, 1));
            tm0 = fmaxf(tm0, __shfl_xor_sync(0xffffffffu, tm0, 2));
            tm1 = fmaxf(tm1, __shfl_xor_sync(0xffffffffu, tm1, 1));
            tm1 = fmaxf(tm1, __shfl_xor_sync(0xffffffffu, tm1, 2));

            float mn0 = fmaxf(m0, tm0), mn1 = fmaxf(m1, tm1);
            float cr0 = __expf(m0 - mn0), cr1 = __expf(m1 - mn1);
            l0 *= cr0; l1 *= cr1;
            #pragma unroll
            for (int nb = 0; nb < 8; nb++) {
                oacc[nb][0] *= cr0; oacc[nb][1] *= cr0;
                oacc[nb][2] *= cr1; oacc[nb][3] *= cr1;
            }
            uint32_t pa01[8], pa23[8];
            #pragma unroll
            for (int nb = 0; nb < 8; nb++) {
                float p0 = __expf(sacc[nb][0] - mn0);
                float p1 = __expf(sacc[nb][1] - mn0);
                float p2 = __expf(sacc[nb][2] - mn1);
                float p3 = __expf(sacc[nb][3] - mn1);
                l0 += p0 + p1; l1 += p2 + p3;
                __half2 h01 = __floats2half2_rn(p0, p1);
                __half2 h23 = __floats2half2_rn(p2, p3);
                pa01[nb] = *(uint32_t*)&h01;
                pa23[nb] = *(uint32_t*)&h23;
            }
            m0 = mn0; m1 = mn1;

            // O += P @ V
            #pragma unroll
            for (int kcc = 0; kcc < 4; kcc++) {
                uint32_t aa[4] = { pa01[2*kcc], pa23[2*kcc], pa01[2*kcc+1], pa23[2*kcc+1] };
                uint32_t bf[8][2];
                #pragma unroll
                for (int pj = 0; pj < 4; pj++) {
                    const __half* p = Vc + (kcc * 16 + vt_row) * KLD + pj * 16 + vt_col;
                    ldmx4t(bf[2*pj][0], bf[2*pj][1], bf[2*pj+1][0], bf[2*pj+1][1], p);
                }
                #pragma unroll
                for (int nb = 0; nb < 8; nb++)
                    mma_f16(oacc[nb], aa, bf[nb]);
            }
        }

        l0 += __shfl_xor_sync(0xffffffffu, l0, 1);
        l0 += __shfl_xor_sync(0xffffffffu, l0, 2);
        l1 += __shfl_xor_sync(0xffffffffu, l1, 1);
        l1 += __shfl_xor_sync(0xffffffffu, l1, 2);
        float i0 = 1.0f / l0, i1 = 1.0f / l1;

        __half* o0 = out + ((size_t)(b * SS) + rg0) * DIM + h * HDIM + 2 * tg;
        __half* o1 = out + ((size_t)(b * SS) + rg1) * DIM + h * HDIM + 2 * tg;
        #pragma unroll
        for (int nb = 0; nb < 8; nb++) {
            *(__half2*)(o0 + nb * 8) = __floats2half2_rn(oacc[nb][0] * i0, oacc[nb][1] * i0);
            *(__half2*)(o1 + nb * 8) = __floats2half2_rn(oacc[nb][2] * i1, oacc[nb][3] * i1);
        }

        // protect smem buffers before next half's loads (all reads of this half done)
        __syncthreads();
    }
}

// ---------------- launch ----------------
extern "C" void kernel_launch(void* const* d_in, const int* in_sizes, int n_in,
                              void* d_out, int out_size) {
    const float* x      = (const float*)d_in[0];
    const float* ln1_w  = (const float*)d_in[1];
    const float* ln1_b  = (const float*)d_in[2];
    const float* qkv_w  = (const float*)d_in[3];
    const float* qkv_b  = (const float*)d_in[4];
    const float* proj_w = (const float*)d_in[5];
    const float* proj_b = (const float*)d_in[6];
    const float* ln2_w  = (const float*)d_in[7];
    const float* ln2_b  = (const float*)d_in[8];
    const float* fc1_w  = (const float*)d_in[9];
    const float* fc1_b  = (const float*)d_in[10];
    const float* fc2_w  = (const float*)d_in[11];
    const float* fc2_b  = (const float*)d_in[12];
    float* out = (float*)d_out;

    __half *xn, *qkv, *attn, *hh, *qkvT, *projT, *fc1T, *fc2T;
    float *x1;
    cudaGetSymbolAddress((void**)&xn,    h_xn);
    cudaGetSymbolAddress((void**)&qkv,   h_qkv);
    cudaGetSymbolAddress((void**)&attn,  h_attn);
    cudaGetSymbolAddress((void**)&x1,    g_x1);
    cudaGetSymbolAddress((void**)&hh,    h_h);
    cudaGetSymbolAddress((void**)&qkvT,  h_qkvT);
    cudaGetSymbolAddress((void**)&projT, h_projT);
    cudaGetSymbolAddress((void**)&fc1T,  h_fc1T);
    cudaGetSymbolAddress((void**)&fc2T,  h_fc2T);

    static cudaStream_t s_tr = nullptr;
    static cudaEvent_t ev_fork = nullptr, ev_qkvT = nullptr, ev_wT = nullptr;
    if (!s_tr) {
        cudaStreamCreateWithFlags(&s_tr, cudaStreamNonBlocking);
        cudaEventCreateWithFlags(&ev_fork, cudaEventDisableTiming);
        cudaEventCreateWithFlags(&ev_qkvT, cudaEventDisableTiming);
        cudaEventCreateWithFlags(&ev_wT,   cudaEventDisableTiming);
    }

    // fork: weight transposes on side stream
    cudaEventRecord(ev_fork, 0);
    cudaStreamWaitEvent(s_tr, ev_fork, 0);
    transpose_h_kernel<<<dim3(3*DIM/32, DIM/32), 256, 0, s_tr>>>(qkv_w, qkvT, DIM, 3*DIM);
    cudaEventRecord(ev_qkvT, s_tr);
    transpose_h_kernel<<<dim3(DIM/32, DIM/32), 256, 0, s_tr>>>(proj_w, projT, DIM, DIM);
    transpose_h_kernel<<<dim3(MLP/32, DIM/32), 256, 0, s_tr>>>(fc1_w, fc1T, DIM, MLP);
    transpose_h_kernel<<<dim3(DIM/32, MLP/32), 256, 0, s_tr>>>(fc2_w, fc2T, MLP, DIM);
    cudaEventRecord(ev_wT, s_tr);

    // main stream
    ln_kernel<<<TT, 256>>>(x, ln1_w, ln1_b, xn);
    cudaStreamWaitEvent(0, ev_qkvT, 0);
    gemm_h<0><<<dim3(3*DIM/128, TT/128), 128>>>(TT, 3*DIM, DIM, xn, qkvT, qkv_b, nullptr, qkv);
    attn_mma<<<dim3(SS/256, BB*HEADS), 256>>>(qkv, attn);
    cudaStreamWaitEvent(0, ev_wT, 0);
    gemm_h<2><<<dim3(DIM/128, TT/128), 128>>>(TT, DIM, DIM, attn, projT, proj_b, x, x1);
    ln_kernel<<<TT, 256>>>(x1, ln2_w, ln2_b, xn);
    gemm_h<1><<<dim3(MLP/128, TT/128), 128>>>(TT, MLP, DIM, xn, fc1T, fc1_b, nullptr, hh);
    gemm_h<2><<<dim3(DIM/128, TT/128), 128>>>(TT, DIM, MLP, hh, fc2T, fc2_b, x1, out);
}

// round 17
// speedup vs baseline: 1.0184x; 1.0001x over previous
#include <cuda_runtime.h>
#include <cuda_fp16.h>
#include <math.h>
#include <stdint.h>

#define DIM   1024
#define HEADS 16
#define HDIM  64
#define MLP   4096
#define BB    4
#define SS    2048
#define TT    (BB*SS)   // 8192 tokens

// ---------------- scratch (device globals; no allocation) ----------------
__device__ __half h_xn[(size_t)TT*DIM];
__device__ __half h_qkv[(size_t)TT*3*DIM];
__device__ __half h_attn[(size_t)TT*DIM];
__device__ float  g_x1[(size_t)TT*DIM];
__device__ __half h_h[(size_t)TT*MLP];
__device__ __half h_qkvT[(size_t)3*DIM*DIM];
__device__ __half h_projT[(size_t)DIM*DIM];
__device__ __half h_fc1T[(size_t)DIM*MLP];
__device__ __half h_fc2T[(size_t)MLP*DIM];

// ---------------- ptx helpers ----------------
__device__ __forceinline__ void mma_f16(float* c, const uint32_t* a, const uint32_t* b) {
    asm volatile(
        "mma.sync.aligned.m16n8k16.row.col.f32.f16.f16.f32 "
        "{%0,%1,%2,%3}, {%4,%5,%6,%7}, {%8,%9}, {%0,%1,%2,%3};"
        : "+f"(c[0]), "+f"(c[1]), "+f"(c[2]), "+f"(c[3])
        : "r"(a[0]), "r"(a[1]), "r"(a[2]), "r"(a[3]), "r"(b[0]), "r"(b[1]));
}

__device__ __forceinline__ void ldmx4(uint32_t& r0, uint32_t& r1, uint32_t& r2, uint32_t& r3,
                                      const __half* p) {
    uint32_t a = (uint32_t)__cvta_generic_to_shared((void*)p);
    asm volatile("ldmatrix.sync.aligned.m8n8.x4.shared.b16 {%0,%1,%2,%3}, [%4];"
                 : "=r"(r0), "=r"(r1), "=r"(r2), "=r"(r3) : "r"(a));
}

__device__ __forceinline__ void ldmx4t(uint32_t& r0, uint32_t& r1, uint32_t& r2, uint32_t& r3,
                                       const __half* p) {
    uint32_t a = (uint32_t)__cvta_generic_to_shared((void*)p);
    asm volatile("ldmatrix.sync.aligned.m8n8.x4.trans.shared.b16 {%0,%1,%2,%3}, [%4];"
                 : "=r"(r0), "=r"(r1), "=r"(r2), "=r"(r3) : "r"(a));
}

__device__ __forceinline__ void cpa16(__half* dst, const __half* src) {
    uint32_t s = (uint32_t)__cvta_generic_to_shared((void*)dst);
    asm volatile("cp.async.cg.shared.global [%0], [%1], 16;" :: "r"(s), "l"(src));
}
#define CP_COMMIT() asm volatile("cp.async.commit_group;" ::: "memory")
#define CP_WAIT2()  asm volatile("cp.async.wait_group 2;" ::: "memory")
#define CP_WAIT1()  asm volatile("cp.async.wait_group 1;" ::: "memory")

// ---------------- LayerNorm: fp32 in -> fp16 out ----------------
__global__ __launch_bounds__(256)
void ln_kernel(const float* __restrict__ x, const float* __restrict__ w,
               const float* __restrict__ b, __half* __restrict__ out) {
    int row = blockIdx.x;
    int tid = threadIdx.x;
    const float4* xr = (const float4*)(x + (size_t)row * DIM);
    float4 v = xr[tid];
    float s  = v.x + v.y + v.z + v.w;
    float ss = v.x*v.x + v.y*v.y + v.z*v.z + v.w*v.w;
    #pragma unroll
    for (int o = 16; o; o >>= 1) {
        s  += __shfl_xor_sync(0xffffffffu, s,  o);
        ss += __shfl_xor_sync(0xffffffffu, ss, o);
    }
    __shared__ float red0[8], red1[8];
    int wid = tid >> 5, lid = tid & 31;
    if (lid == 0) { red0[wid] = s; red1[wid] = ss; }
    __syncthreads();
    float sum = 0.f, sumsq = 0.f;
    #pragma unroll
    for (int i = 0; i < 8; i++) { sum += red0[i]; sumsq += red1[i]; }
    float mu   = sum * (1.0f / DIM);
    float var  = sumsq * (1.0f / DIM) - mu * mu;
    float rstd = rsqrtf(var + 1e-5f);
    float4 wv = ((const float4*)w)[tid];
    float4 bv = ((const float4*)b)[tid];
    __half2* o2 = (__half2*)(out + (size_t)row * DIM);
    o2[tid*2+0] = __floats2half2_rn((v.x - mu)*rstd*wv.x + bv.x,
                                    (v.y - mu)*rstd*wv.y + bv.y);
    o2[tid*2+1] = __floats2half2_rn((v.z - mu)*rstd*wv.z + bv.z,
                                    (v.w - mu)*rstd*wv.w + bv.w);
}

// ---------------- weight transpose [K,N] fp32 -> [N,K] fp16 ----------------
__global__ __launch_bounds__(256)
void transpose_h_kernel(const float* __restrict__ in, __half* __restrict__ out,
                        int K, int N) {
    __shared__ float tile[32][33];
    int bx = blockIdx.x;
    int by = blockIdx.y;
    int tx = threadIdx.x & 31;
    int ty = threadIdx.x >> 5;
    #pragma unroll
    for (int i = 0; i < 32; i += 8)
        tile[ty + i][tx] = in[(size_t)(by * 32 + ty + i) * N + bx * 32 + tx];
    __syncthreads();
    #pragma unroll
    for (int i = 0; i < 32; i += 8)
        out[(size_t)(bx * 32 + ty + i) * K + by * 32 + tx] = __float2half_rn(tile[tx][ty + i]);
}

// ---------------- fp16 mma GEMM, 4-stage cp.async + ldmatrix, 1 sync/chunk ----------------
#define GLDA 40
#define STG_H (2 * 128 * GLDA)

template <int EPI>
__global__ __launch_bounds__(128, 2)
void gemm_h(int M, int N, int K,
            const __half* __restrict__ A, const __half* __restrict__ Bt,
            const float* __restrict__ bias, const float* __restrict__ R,
            void* __restrict__ Cout) {
    __shared__ __half sh[4 * STG_H];

    int tid = threadIdx.x;
    int wid = tid >> 5, lane = tid & 31;
    int gid = lane >> 2, tg = lane & 3;
    int wm = wid & 1, wn = wid >> 1;
    int bx = blockIdx.x, by = blockIdx.y;

    const __half* Ab = A  + (size_t)(by * 128) * K;
    const __half* Bb = Bt + (size_t)(bx * 128) * K;

    float acc[4][8][4];
    #pragma unroll
    for (int i = 0; i < 4; i++)
        #pragma unroll
        for (int j = 0; j < 8; j++)
            #pragma unroll
            for (int c = 0; c < 4; c++) acc[i][j][c] = 0.f;

    int NC = K / 32;

    auto issue = [&](int s) {
        if (s < NC) {
            __half* sa = sh + (s & 3) * STG_H;
            __half* sb = sa + 128 * GLDA;
            int kb = s * 32;
            #pragma unroll
            for (int it = 0; it < 4; it++) {
                int idx = it * 128 + tid;
                int r = idx >> 2, c8 = (idx & 3) * 8;
                cpa16(sa + r * GLDA + c8, Ab + (size_t)r * K + kb + c8);
                cpa16(sb + r * GLDA + c8, Bb + (size_t)r * K + kb + c8);
            }
        }
        CP_COMMIT();
    };

    issue(0); issue(1); issue(2);

    for (int kc = 0; kc < NC; kc++) {
        CP_WAIT2();
        __syncthreads();
        issue(kc + 3);   // refills buffer (kc-1)&3: all warps past compute(kc-1)

        const __half* Ac = sh + (kc & 3) * STG_H;
        const __half* Bc = Ac + 128 * GLDA;

        #pragma unroll
        for (int kk = 0; kk < 32; kk += 16) {
            uint32_t af[4][4];
            #pragma unroll
            for (int mf = 0; mf < 4; mf++) {
                const __half* p = Ac + (wm * 64 + mf * 16 + (lane & 15)) * GLDA
                                  + kk + (lane >> 4) * 8;
                ldmx4(af[mf][0], af[mf][1], af[mf][2], af[mf][3], p);
            }
            uint32_t bf[8][2];
            #pragma unroll
            for (int pj = 0; pj < 4; pj++) {
                const __half* p = Bc + (wn * 64 + (pj * 2 + (lane >> 4)) * 8 + (lane & 7)) * GLDA
                                  + kk + ((lane >> 3) & 1) * 8;
                ldmx4(bf[2*pj][0], bf[2*pj][1], bf[2*pj+1][0], bf[2*pj+1][1], p);
            }
            #pragma unroll
            for (int mf = 0; mf < 4; mf++)
                #pragma unroll
                for (int nb = 0; nb < 8; nb++)
                    mma_f16(acc[mf][nb], af[mf], bf[nb]);
        }
    }

    // epilogue
    int colW = bx * 128 + wn * 64;
    #pragma unroll
    for (int mf = 0; mf < 4; mf++) {
        #pragma unroll
        for (int r2 = 0; r2 < 2; r2++) {
            int row = by * 128 + wm * 64 + mf * 16 + gid + r2 * 8;
            #pragma unroll
            for (int nb = 0; nb < 8; nb++) {
                int gcol = colW + nb * 8 + 2 * tg;
                float t0 = acc[mf][nb][r2 * 2 + 0] + bias[gcol];
                float t1 = acc[mf][nb][r2 * 2 + 1] + bias[gcol + 1];
                if (EPI == 1) {
                    t0 = 0.5f * t0 * (1.0f + erff(t0 * 0.70710678118654752f));
                    t1 = 0.5f * t1 * (1.0f + erff(t1 * 0.70710678118654752f));
                }
                if (EPI == 2) {
                    float2 rv = *(const float2*)(R + (size_t)row * N + gcol);
                    t0 += rv.x; t1 += rv.y;
                    *(float2*)((float*)Cout + (size_t)row * N + gcol) = make_float2(t0, t1);
                } else {
                    *(__half2*)((__half*)Cout + (size_t)row * N + gcol) = __floats2half2_rn(t0, t1);
                }
            }
        }
    }
}

// ---------------- causal flash attention: paired q-tiles, occupancy 2 ----------------
// grid (8, B*H): CTA bx handles q-tiles bx and 15-bx => every CTA does exactly 36 tile-steps.
#define KLD 72
#define ATILE (64 * KLD)

__global__ __launch_bounds__(256, 2)
void attn_mma(const __half* __restrict__ qkv, __half* __restrict__ out) {
    int bh = blockIdx.y;
    int b = bh >> 4, h = bh & 15;
    int tid = threadIdx.x;
    int wid = tid >> 5, lane = tid & 31;
    int gid = lane >> 2, tg = lane & 3;

    __shared__ __half Ks3[3 * ATILE];   // [key][dim]
    __shared__ __half Vs3[3 * ATILE];   // [key][dim]

    int lm_row = ((lane >> 4)) * 8 + (lane & 7);
    int lm_koff = ((lane >> 3) & 1) * 8;
    int vt_row = (lane & 7) + ((lane >> 3) & 1) * 8;
    int vt_col = (lane >> 4) * 8;

    #pragma unroll 1
    for (int half = 0; half < 2; half++) {
        int qt = half ? (15 - blockIdx.x) : blockIdx.x;
        int q0 = qt * 128;
        int ntiles = 2 * qt + 2;

        auto issueA = [&](int s) {
            if (s < ntiles) {
                __half* ka = Ks3 + (s % 3) * ATILE;
                __half* va = Vs3 + (s % 3) * ATILE;
                #pragma unroll
                for (int it = 0; it < 2; it++) {
                    int idx = it * 256 + tid;
                    int r = idx >> 3, c8 = (idx & 7) * 8;
                    const __half* src = qkv + ((size_t)(b * SS) + s * 64 + r) * (3 * DIM) + h * HDIM + c8;
                    cpa16(ka + r * KLD + c8, src + DIM);
                    cpa16(va + r * KLD + c8, src + 2 * DIM);
                }
            }
            CP_COMMIT();
        };

        uint32_t qa[4][4];
        {
            const __half* Q0 = qkv + ((size_t)(b * SS) + q0 + wid * 16 + gid) * (3 * DIM) + h * HDIM + 2 * tg;
            const __half* Q1 = Q0 + (size_t)8 * (3 * DIM);
            #pragma unroll
            for (int kcc = 0; kcc < 4; kcc++) {
                qa[kcc][0] = *(const uint32_t*)(Q0 + kcc * 16);
                qa[kcc][1] = *(const uint32_t*)(Q1 + kcc * 16);
                qa[kcc][2] = *(const uint32_t*)(Q0 + kcc * 16 + 8);
                qa[kcc][3] = *(const uint32_t*)(Q1 + kcc * 16 + 8);
            }
        }

        issueA(0); issueA(1);

        float oacc[8][4];
        #pragma unroll
        for (int nb = 0; nb < 8; nb++)
            #pragma unroll
            for (int c = 0; c < 4; c++) oacc[nb][c] = 0.f;
        float m0 = -1e30f, m1 = -1e30f, l0 = 0.f, l1 = 0.f;
        int rg0 = q0 + wid * 16 + gid;
        int rg1 = rg0 + 8;

        for (int jt = 0; jt < ntiles; jt++) {
            CP_WAIT1();
            __syncthreads();
            issueA(jt + 2);

            const __half* Kc = Ks3 + (jt % 3) * ATILE;
            const __half* Vc = Vs3 + (jt % 3) * ATILE;

            // S = Q @ K^T
            float sacc[8][4];
            #pragma unroll
            for (int nb = 0; nb < 8; nb++)
                #pragma unroll
                for (int c = 0; c < 4; c++) sacc[nb][c] = 0.f;
            #pragma unroll
            for (int kcc = 0; kcc < 4; kcc++) {
                uint32_t bf[8][2];
                #pragma unroll
                for (int pj = 0; pj < 4; pj++) {
                    const __half* p = Kc + (pj * 16 + lm_row) * KLD + kcc * 16 + lm_koff;
                    ldmx4(bf[2*pj][0], bf[2*pj][1], bf[2*pj+1][0], bf[2*pj+1][1], p);
                }
                #pragma unroll
                for (int nb = 0; nb < 8; nb++)
                    mma_f16(sacc[nb], qa[kcc], bf[nb]);
            }

            const float sc = 0.125f;
            float tm0 = -1e30f, tm1 = -1e30f;
            bool need_mask = (jt >= 2 * qt);
            #pragma unroll
            for (int nb = 0; nb < 8; nb++) {
                int col = jt * 64 + nb * 8 + 2 * tg;
                float s0 = sacc[nb][0] * sc, s1 = sacc[nb][1] * sc;
                float s2 = sacc[nb][2] * sc, s3 = sacc[nb][3] * sc;
                if (need_mask) {
                    if (col     > rg0) s0 = -1e30f;
                    if (col + 1 > rg0) s1 = -1e30f;
                    if (col     > rg1) s2 = -1e30f;
                    if (col + 1 > rg1) s3 = -1e30f;
                }
                sacc[nb][0] = s0; sacc[nb][1] = s1; sacc[nb][2] = s2; sacc[nb][3] = s3;
                tm0 = fmaxf(tm0, fmaxf(s0, s1));
                tm1 = fmaxf(tm1, fmaxf(s2, s3));
            }
            tm0 = fmaxf(tm0, __shfl_xor_sync(0xffffffffu, tm0, 1));
            tm0 = fmaxf(tm0, __shfl_xor_sync(0xffffffffu, tm0, 2));
            tm1 = fmaxf(tm1, __shfl_xor_sync(0xffffffffu, tm1, 1));
            tm1 = fmaxf(tm1, __shfl_xor_sync(0xffffffffu, tm1, 2));

            float mn0 = fmaxf(m0, tm0), mn1 = fmaxf(m1, tm1);
            float cr0 = __expf(m0 - mn0), cr1 = __expf(m1 - mn1);
            l0 *= cr0; l1 *= cr1;
            #pragma unroll
            for (int nb = 0; nb < 8; nb++) {
                oacc[nb][0] *= cr0; oacc[nb][1] *= cr0;
                oacc[nb][2] *= cr1; oacc[nb][3] *= cr1;
            }
            uint32_t pa01[8], pa23[8];
            #pragma unroll
            for (int nb = 0; nb < 8; nb++) {
                float p0 = __expf(sacc[nb][0] - mn0);
                float p1 = __expf(sacc[nb][1] - mn0);
                float p2 = __expf(sacc[nb][2] - mn1);
                float p3 = __expf(sacc[nb][3] - mn1);
                l0 += p0 + p1; l1 += p2 + p3;
                __half2 h01 = __floats2half2_rn(p0, p1);
                __half2 h23 = __floats2half2_rn(p2, p3);
                pa01[nb] = *(uint32_t*)&h01;
                pa23[nb] = *(uint32_t*)&h23;
            }
            m0 = mn0; m1 = mn1;

            // O += P @ V
            #pragma unroll
            for (int kcc = 0; kcc < 4; kcc++) {
                uint32_t aa[4] = { pa01[2*kcc], pa23[2*kcc], pa01[2*kcc+1], pa23[2*kcc+1] };
                uint32_t bf[8][2];
                #pragma unroll
                for (int pj = 0; pj < 4; pj++) {
                    const __half* p = Vc + (kcc * 16 + vt_row) * KLD + pj * 16 + vt_col;
                    ldmx4t(bf[2*pj][0], bf[2*pj][1], bf[2*pj+1][0], bf[2*pj+1][1], p);
                }
                #pragma unroll
                for (int nb = 0; nb < 8; nb++)
                    mma_f16(oacc[nb], aa, bf[nb]);
            }
        }

        l0 += __shfl_xor_sync(0xffffffffu, l0, 1);
        l0 += __shfl_xor_sync(0xffffffffu, l0, 2);
        l1 += __shfl_xor_sync(0xffffffffu, l1, 1);
        l1 += __shfl_xor_sync(0xffffffffu, l1, 2);
        float i0 = 1.0f / l0, i1 = 1.0f / l1;

        __half* o0 = out + ((size_t)(b * SS) + rg0) * DIM + h * HDIM + 2 * tg;
        __half* o1 = out + ((size_t)(b * SS) + rg1) * DIM + h * HDIM + 2 * tg;
        #pragma unroll
        for (int nb = 0; nb < 8; nb++) {
            *(__half2*)(o0 + nb * 8) = __floats2half2_rn(oacc[nb][0] * i0, oacc[nb][1] * i0);
            *(__half2*)(o1 + nb * 8) = __floats2half2_rn(oacc[nb][2] * i1, oacc[nb][3] * i1);
        }

        // protect smem buffers before next half's loads (all reads of this half done)
        __syncthreads();
    }
}

// ---------------- launch ----------------
extern "C" void kernel_launch(void* const* d_in, const int* in_sizes, int n_in,
                              void* d_out, int out_size) {
    const float* x      = (const float*)d_in[0];
    const float* ln1_w  = (const float*)d_in[1];
    const float* ln1_b  = (const float*)d_in[2];
    const float* qkv_w  = (const float*)d_in[3];
    const float* qkv_b  = (const float*)d_in[4];
    const float* proj_w = (const float*)d_in[5];
    const float* proj_b = (const float*)d_in[6];
    const float* ln2_w  = (const float*)d_in[7];
    const float* ln2_b  = (const float*)d_in[8];
    const float* fc1_w  = (const float*)d_in[9];
    const float* fc1_b  = (const float*)d_in[10];
    const float* fc2_w  = (const float*)d_in[11];
    const float* fc2_b  = (const float*)d_in[12];
    float* out = (float*)d_out;

    __half *xn, *qkv, *attn, *hh, *qkvT, *projT, *fc1T, *fc2T;
    float *x1;
    cudaGetSymbolAddress((void**)&xn,    h_xn);
    cudaGetSymbolAddress((void**)&qkv,   h_qkv);
    cudaGetSymbolAddress((void**)&attn,  h_attn);
    cudaGetSymbolAddress((void**)&x1,    g_x1);
    cudaGetSymbolAddress((void**)&hh,    h_h);
    cudaGetSymbolAddress((void**)&qkvT,  h_qkvT);
    cudaGetSymbolAddress((void**)&projT, h_projT);
    cudaGetSymbolAddress((void**)&fc1T,  h_fc1T);
    cudaGetSymbolAddress((void**)&fc2T,  h_fc2T);

    static cudaStream_t s_tr = nullptr;
    static cudaEvent_t ev_fork = nullptr, ev_qkvT = nullptr, ev_wT = nullptr;
    if (!s_tr) {
        cudaStreamCreateWithFlags(&s_tr, cudaStreamNonBlocking);
        cudaEventCreateWithFlags(&ev_fork, cudaEventDisableTiming);
        cudaEventCreateWithFlags(&ev_qkvT, cudaEventDisableTiming);
        cudaEventCreateWithFlags(&ev_wT,   cudaEventDisableTiming);
    }

    // fork: weight transposes on side stream
    cudaEventRecord(ev_fork, 0);
    cudaStreamWaitEvent(s_tr, ev_fork, 0);
    transpose_h_kernel<<<dim3(3*DIM/32, DIM/32), 256, 0, s_tr>>>(qkv_w, qkvT, DIM, 3*DIM);
    cudaEventRecord(ev_qkvT, s_tr);
    transpose_h_kernel<<<dim3(DIM/32, DIM/32), 256, 0, s_tr>>>(proj_w, projT, DIM, DIM);
    transpose_h_kernel<<<dim3(MLP/32, DIM/32), 256, 0, s_tr>>>(fc1_w, fc1T, DIM, MLP);
    transpose_h_kernel<<<dim3(DIM/32, MLP/32), 256, 0, s_tr>>>(fc2_w, fc2T, MLP, DIM);
    cudaEventRecord(ev_wT, s_tr);

    // main stream
    ln_kernel<<<TT, 256>>>(x, ln1_w, ln1_b, xn);
    cudaStreamWaitEvent(0, ev_qkvT, 0);
    gemm_h<0><<<dim3(3*DIM/128, TT/128), 128>>>(TT, 3*DIM, DIM, xn, qkvT, qkv_b, nullptr, qkv);
    attn_mma<<<dim3(SS/256, BB*HEADS), 256>>>(qkv, attn);
    cudaStreamWaitEvent(0, ev_wT, 0);
    gemm_h<2><<<dim3(DIM/128, TT/128), 128>>>(TT, DIM, DIM, attn, projT, proj_b, x, x1);
    ln_kernel<<<TT, 256>>>(x1, ln2_w, ln2_b, xn);
    gemm_h<1><<<dim3(MLP/128, TT/128), 128>>>(TT, MLP, DIM, xn, fc1T, fc1_b, nullptr, hh);
    gemm_h<2><<<dim3(DIM/128, TT/128), 128>>>(TT, DIM, MLP, hh, fc2T, fc2_b, x1, out);
}